// round 15
// baseline (speedup 1.0000x reference)
#include <cuda_runtime.h>
#include <cuda_bf16.h>
#include <math.h>
#include <stdint.h>

typedef unsigned long long ull;

#define T_LEN 1024
#define B_DIM 256
#define H_DIM 128
#define BH (B_DIM * H_DIM)          // 32768
#define R_TOT (T_LEN * B_DIM)       // 262144
#define N_TILES (R_TOT / 128)       // 2048
#define PGRID 148                   // persistent grid: one CTA per SM

__device__ float g_z[(size_t)T_LEN * BH];
__device__ float g_h[(size_t)T_LEN * BH];

// Pre-split weight images, padded to the exact smem layouts (bf16)
__device__ __align__(16) __nv_bfloat16 g_wx_h[128 * 72],  g_wx_l[128 * 72];    // LDA1=72
__device__ __align__(16) __nv_bfloat16 g_wih_h[128 * 136], g_wih_l[128 * 136]; // LDW=136
__device__ __align__(16) __nv_bfloat16 g_wh_h[128 * 136],  g_wh_l[128 * 136];
__device__ __align__(16) __nv_bfloat16 g_wg_h[64 * 136],   g_wg_l[64 * 136];

// ---------------- helpers ----------------
__device__ __forceinline__ uint32_t smaddr(const void* p) {
    uint32_t a;
    asm("{ .reg .u64 t; cvta.to.shared.u64 t, %1; cvt.u32.u64 %0, t; }" : "=r"(a) : "l"(p));
    return a;
}
__device__ __forceinline__ uint32_t cvt_bf2(float lo, float hi) {
    uint32_t r;
    asm("cvt.rn.bf16x2.f32 %0, %1, %2;" : "=r"(r) : "f"(hi), "f"(lo));
    return r;
}
__device__ __forceinline__ float lo2f(uint32_t w) { return __uint_as_float(w << 16); }
__device__ __forceinline__ float hi2f(uint32_t w) { return __uint_as_float(w & 0xFFFF0000u); }
__device__ __forceinline__ void split2(float vx, float vy, uint32_t& hi, uint32_t& lo) {
    hi = cvt_bf2(vx, vy);
    lo = cvt_bf2(vx - lo2f(hi), vy - hi2f(hi));
}

#define LDSM4(r0, r1, r2, r3, addr) \
    asm volatile("ldmatrix.sync.aligned.m8n8.x4.shared.b16 {%0,%1,%2,%3}, [%4];" \
                 : "=r"(r0), "=r"(r1), "=r"(r2), "=r"(r3) : "r"(addr))

__device__ __forceinline__ void mma16816(float* d, uint32_t a0, uint32_t a1, uint32_t a2, uint32_t a3,
                                         uint32_t b0, uint32_t b1) {
    asm volatile(
        "mma.sync.aligned.m16n8k16.row.col.f32.bf16.bf16.f32 "
        "{%0,%1,%2,%3}, {%4,%5,%6,%7}, {%8,%9}, {%0,%1,%2,%3};"
        : "+f"(d[0]), "+f"(d[1]), "+f"(d[2]), "+f"(d[3])
        : "r"(a0), "r"(a1), "r"(a2), "r"(a3), "r"(b0), "r"(b1));
}

// Warp-level split-bf16 GEMM: acc[MT][NT][4] += (Ahi+Alo) @ (Bhi+Blo)^T (3 combos)
template<int MT, int NT, int KS, int LDA, int LDB>
__device__ __forceinline__ void warp_gemm3(
    uint32_t Ah, uint32_t Al, uint32_t Bh, uint32_t Bl,
    int mbase, int nbase, int lane, float (&acc)[MT][NT][4])
{
    const uint32_t dA = Al - Ah;
    const uint32_t dB = Bl - Bh;
    uint32_t aAddr[MT];
    #pragma unroll
    for (int mt = 0; mt < MT; mt++)
        aAddr[mt] = Ah + (uint32_t)(((mbase + mt * 16 + (lane & 15)) * LDA + (lane >> 4) * 8) * 2);
    uint32_t bAddr[NT / 2];
    #pragma unroll
    for (int p = 0; p < NT / 2; p++)
        bAddr[p] = Bh + (uint32_t)(((nbase + p * 16 + (lane >> 4) * 8 + (lane & 7)) * LDB
                                    + ((lane >> 3) & 1) * 8) * 2);

    #pragma unroll
    for (int ks = 0; ks < KS; ks++) {
        const uint32_t ko = ks * 32;
        uint32_t ah[MT][4], al[MT][4];
        #pragma unroll
        for (int mt = 0; mt < MT; mt++) {
            LDSM4(ah[mt][0], ah[mt][1], ah[mt][2], ah[mt][3], aAddr[mt] + ko);
            LDSM4(al[mt][0], al[mt][1], al[mt][2], al[mt][3], aAddr[mt] + ko + dA);
        }
        uint32_t bh[NT][2], bl[NT][2];
        #pragma unroll
        for (int p = 0; p < NT / 2; p++) {
            LDSM4(bh[2 * p][0], bh[2 * p][1], bh[2 * p + 1][0], bh[2 * p + 1][1], bAddr[p] + ko);
            LDSM4(bl[2 * p][0], bl[2 * p][1], bl[2 * p + 1][0], bl[2 * p + 1][1], bAddr[p] + ko + dB);
        }
        #pragma unroll
        for (int mt = 0; mt < MT; mt++)
            #pragma unroll
            for (int nt = 0; nt < NT; nt++) {
                mma16816(acc[mt][nt], ah[mt][0], ah[mt][1], ah[mt][2], ah[mt][3], bh[nt][0], bh[nt][1]);
                mma16816(acc[mt][nt], ah[mt][0], ah[mt][1], ah[mt][2], ah[mt][3], bl[nt][0], bl[nt][1]);
                mma16816(acc[mt][nt], al[mt][0], al[mt][1], al[mt][2], al[mt][3], bh[nt][0], bh[nt][1]);
            }
    }
}

__device__ __forceinline__ void cp16(void* d, const void* s, int bytes, int tid, int nthr) {
    uint4* dd = (uint4*)d;
    const uint4* ss = (const uint4*)s;
    for (int i = tid; i < bytes / 16; i += nthr) dd[i] = ss[i];
}

// =====================================================================
// Weight pre-split (once per launch)
// =====================================================================
__global__ void split_weights_kernel(const float* __restrict__ Wx, const float* __restrict__ Wih,
                                     const float* __restrict__ Wh, const float* __restrict__ Wg)
{
    int idx = blockIdx.x * 256 + threadIdx.x;
    const float* W; __nv_bfloat16 *hi, *lo; int K, LD, local;
    if (idx < 8192)       { W = Wx;  hi = g_wx_h;  lo = g_wx_l;  K = 64;  LD = 72;  local = idx; }
    else if (idx < 24576) { W = Wih; hi = g_wih_h; lo = g_wih_l; K = 128; LD = 136; local = idx - 8192; }
    else if (idx < 40960) { W = Wh;  hi = g_wh_h;  lo = g_wh_l;  K = 128; LD = 136; local = idx - 24576; }
    else if (idx < 49152) { W = Wg;  hi = g_wg_h;  lo = g_wg_l;  K = 128; LD = 136; local = idx - 40960; }
    else return;
    int n = local / K, k = local % K;
    float v = W[local];
    __nv_bfloat16 h = __float2bfloat16(v);
    float r = v - __bfloat162float(h);
    hi[n * LD + k] = h;
    lo[n * LD + k] = __float2bfloat16(r);
}

// =====================================================================
// Phase 1: z = tanh(x @ Wx^T + b_x) @ Wih^T + b_ih        [R_TOT, 128]
// Persistent, 1024 threads (32 warps = 8/SMSP), warp grid 8m x 4n.
// =====================================================================
#define PTHREADS 1024
#define LDA1 72
#define LDW  136
#define P1_A1H 0
#define P1_A1L 18432
#define P1_B1H 36864
#define P1_B1L 55296
#define P1_B2H 73728
#define P1_B2L 108544
#define P1_FH  143360
#define P1_FL  178176
#define P1_DYN 212992

__global__ __launch_bounds__(PTHREADS) void phase1_mma(
    const float* __restrict__ x, const float* __restrict__ b_x,
    const float* __restrict__ b_ih)
{
    extern __shared__ __align__(16) unsigned char sm[];
    __shared__ float s_bx[128], s_bih[128];

    const int tid = threadIdx.x, lane = tid & 31, wid = tid >> 5;
    const int wm = wid >> 2, wn = wid & 3;          // 8m x 4n
    const uint32_t sb = smaddr(sm);

    if (tid < 128) { s_bx[tid] = b_x[tid]; s_bih[tid] = b_ih[tid]; }

    // weights: loaded ONCE per CTA
    cp16(sm + P1_B1H, g_wx_h, 18432, tid, PTHREADS);
    cp16(sm + P1_B1L, g_wx_l, 18432, tid, PTHREADS);
    cp16(sm + P1_B2H, g_wih_h, 34816, tid, PTHREADS);
    cp16(sm + P1_B2L, g_wih_l, 34816, tid, PTHREADS);

    for (int tile = blockIdx.x; tile < N_TILES; tile += PGRID) {
        const int row0 = tile * 128;

        // x tile [128m][64k] -> split (no live readers of A1 here)
        {
            const float2* xg = (const float2*)(x + (size_t)row0 * 64);
            for (int p = tid; p < 4096; p += PTHREADS) {
                int m = p >> 5, kp = (p & 31) * 2;
                float2 v = xg[p];
                uint32_t hi, lo; split2(v.x, v.y, hi, lo);
                *(uint32_t*)(sm + P1_A1H + (m * LDA1 + kp) * 2) = hi;
                *(uint32_t*)(sm + P1_A1L + (m * LDA1 + kp) * 2) = lo;
            }
        }
        __syncthreads();

        float acc[1][4][4];
        #pragma unroll
        for (int b = 0; b < 4; b++)
            #pragma unroll
            for (int c = 0; c < 4; c++) acc[0][b][c] = 0.0f;

        warp_gemm3<1, 4, 4, LDA1, LDA1>(sb + P1_A1H, sb + P1_A1L, sb + P1_B1H, sb + P1_B1L,
                                        wm * 16, wn * 32, lane, acc);

        #pragma unroll
        for (int nt = 0; nt < 4; nt++) {
            int row = wm * 16 + (lane >> 2);
            int col = wn * 32 + nt * 8 + 2 * (lane & 3);
            float t0 = tanhf(acc[0][nt][0] + s_bx[col]);
            float t1 = tanhf(acc[0][nt][1] + s_bx[col + 1]);
            uint32_t hi, lo; split2(t0, t1, hi, lo);
            *(uint32_t*)(sm + P1_FH + (row * LDW + col) * 2) = hi;
            *(uint32_t*)(sm + P1_FL + (row * LDW + col) * 2) = lo;
            float t2 = tanhf(acc[0][nt][2] + s_bx[col]);
            float t3 = tanhf(acc[0][nt][3] + s_bx[col + 1]);
            split2(t2, t3, hi, lo);
            *(uint32_t*)(sm + P1_FH + ((row + 8) * LDW + col) * 2) = hi;
            *(uint32_t*)(sm + P1_FL + ((row + 8) * LDW + col) * 2) = lo;
        }
        __syncthreads();

        #pragma unroll
        for (int b = 0; b < 4; b++)
            #pragma unroll
            for (int c = 0; c < 4; c++) acc[0][b][c] = 0.0f;

        warp_gemm3<1, 4, 8, LDW, LDW>(sb + P1_FH, sb + P1_FL, sb + P1_B2H, sb + P1_B2L,
                                      wm * 16, wn * 32, lane, acc);

        #pragma unroll
        for (int nt = 0; nt < 4; nt++) {
            int row = row0 + wm * 16 + (lane >> 2);
            int col = wn * 32 + nt * 8 + 2 * (lane & 3);
            float2 v0 = make_float2(acc[0][nt][0] + s_bih[col], acc[0][nt][1] + s_bih[col + 1]);
            float2 v1 = make_float2(acc[0][nt][2] + s_bih[col], acc[0][nt][3] + s_bih[col + 1]);
            *(float2*)(g_z + (size_t)row * 128 + col) = v0;
            *(float2*)(g_z + (size_t)(row + 8) * 128 + col) = v1;
        }
    }
}

// =====================================================================
// Phase 3: y = tanh(h @ Wh^T + b_h) @ Wg^T + b_g          [R_TOT, 64]
// Persistent, 1024 threads, warp grid 8m x 4n (gemm2: NT=2).
// =====================================================================
#define P3_A1H 0
#define P3_A1L 34816
#define P3_B1H 69632
#define P3_B1L 104448
#define P3_B2H 139264
#define P3_B2L 156672
#define P3_DYN 174080

__global__ __launch_bounds__(PTHREADS) void phase3_mma(
    const float* __restrict__ b_h, const float* __restrict__ b_g,
    float* __restrict__ y)
{
    extern __shared__ __align__(16) unsigned char sm[];
    __shared__ float s_bh[128], s_bg[64];

    const int tid = threadIdx.x, lane = tid & 31, wid = tid >> 5;
    const int wm = wid >> 2, wn = wid & 3;          // 8m x 4n
    const uint32_t sb = smaddr(sm);

    if (tid < 128) s_bh[tid] = b_h[tid];
    if (tid < 64)  s_bg[tid] = b_g[tid];

    cp16(sm + P3_B1H, g_wh_h, 34816, tid, PTHREADS);
    cp16(sm + P3_B1L, g_wh_l, 34816, tid, PTHREADS);
    cp16(sm + P3_B2H, g_wg_h, 17408, tid, PTHREADS);
    cp16(sm + P3_B2L, g_wg_l, 17408, tid, PTHREADS);

    bool first = true;
    for (int tile = blockIdx.x; tile < N_TILES; tile += PGRID) {
        const int row0 = tile * 128;

        if (!first) __syncthreads();   // gemm2 readers of A1 (u) must finish
        first = false;

        // h tile [128m][128k] -> split
        {
            const float2* hg = (const float2*)(g_h + (size_t)row0 * 128);
            for (int p = tid; p < 8192; p += PTHREADS) {
                int m = p >> 6, kp = (p & 63) * 2;
                float2 v = hg[p];
                uint32_t hi, lo; split2(v.x, v.y, hi, lo);
                *(uint32_t*)(sm + P3_A1H + (m * LDW + kp) * 2) = hi;
                *(uint32_t*)(sm + P3_A1L + (m * LDW + kp) * 2) = lo;
            }
        }
        __syncthreads();

        float acc[1][4][4];
        #pragma unroll
        for (int b = 0; b < 4; b++)
            #pragma unroll
            for (int c = 0; c < 4; c++) acc[0][b][c] = 0.0f;

        warp_gemm3<1, 4, 8, LDW, LDW>(sb + P3_A1H, sb + P3_A1L, sb + P3_B1H, sb + P3_B1L,
                                      wm * 16, wn * 32, lane, acc);
        __syncthreads();   // all reads of A1 done before in-place overwrite

        #pragma unroll
        for (int nt = 0; nt < 4; nt++) {
            int row = wm * 16 + (lane >> 2);
            int col = wn * 32 + nt * 8 + 2 * (lane & 3);
            float t0 = tanhf(acc[0][nt][0] + s_bh[col]);
            float t1 = tanhf(acc[0][nt][1] + s_bh[col + 1]);
            uint32_t hi, lo; split2(t0, t1, hi, lo);
            *(uint32_t*)(sm + P3_A1H + (row * LDW + col) * 2) = hi;
            *(uint32_t*)(sm + P3_A1L + (row * LDW + col) * 2) = lo;
            float t2 = tanhf(acc[0][nt][2] + s_bh[col]);
            float t3 = tanhf(acc[0][nt][3] + s_bh[col + 1]);
            split2(t2, t3, hi, lo);
            *(uint32_t*)(sm + P3_A1H + ((row + 8) * LDW + col) * 2) = hi;
            *(uint32_t*)(sm + P3_A1L + ((row + 8) * LDW + col) * 2) = lo;
        }
        __syncthreads();

        float ac2[1][2][4];
        #pragma unroll
        for (int b = 0; b < 2; b++)
            #pragma unroll
            for (int c = 0; c < 4; c++) ac2[0][b][c] = 0.0f;

        warp_gemm3<1, 2, 8, LDW, LDW>(sb + P3_A1H, sb + P3_A1L, sb + P3_B2H, sb + P3_B2L,
                                      wm * 16, wn * 16, lane, ac2);

        #pragma unroll
        for (int nt = 0; nt < 2; nt++) {
            int row = row0 + wm * 16 + (lane >> 2);
            int col = wn * 16 + nt * 8 + 2 * (lane & 3);
            float2 v0 = make_float2(ac2[0][nt][0] + s_bg[col], ac2[0][nt][1] + s_bg[col + 1]);
            float2 v1 = make_float2(ac2[0][nt][2] + s_bg[col], ac2[0][nt][3] + s_bg[col + 1]);
            *(float2*)(y + (size_t)row * 64 + col) = v0;
            *(float2*)(y + (size_t)(row + 8) * 64 + col) = v1;
        }
    }
}

// =====================================================================
// Phase 2: recurrence — EXACT round-1 measured-best version (untouched).
// =====================================================================
__device__ __forceinline__ ull pk2(float lo, float hi) {
    ull r;
    asm("mov.b64 %0, {%1,%2};" : "=l"(r) : "r"(__float_as_uint(lo)), "r"(__float_as_uint(hi)));
    return r;
}
__device__ __forceinline__ float2 upk2(ull v) {
    unsigned int lo, hi;
    asm("mov.b64 {%0,%1}, %2;" : "=r"(lo), "=r"(hi) : "l"(v));
    return make_float2(__uint_as_float(lo), __uint_as_float(hi));
}
__device__ __forceinline__ void fma2(ull& d, ull a, ull b) {
    asm("fma.rn.f32x2 %0, %1, %2, %0;" : "+l"(d) : "l"(a), "l"(b));
}

__global__ __launch_bounds__(128, 3) void rnn_kernel(
    const float* __restrict__ W_hh, const float* __restrict__ b_hh)
{
    __shared__ __align__(16) float hs[128];

    const int b = blockIdx.x;
    const int j = threadIdx.x;

    ull w[64];
    const ulonglong2* w2 = (const ulonglong2*)(W_hh + j * 128);
    #pragma unroll
    for (int i = 0; i < 32; i++) {
        ulonglong2 v = w2[i];
        w[2 * i]     = v.x;
        w[2 * i + 1] = v.y;
    }
    const float bh = b_hh[j];

    hs[j] = 0.0f;
    g_h[(size_t)b * 128 + j] = 0.0f;                 // h_0 = 0
    float zreg = g_z[(size_t)b * 128 + j];           // z_0
    __syncthreads();

    for (int t = 0; t < T_LEN - 1; ++t) {
        float znext = 0.0f;
        if (t < T_LEN - 2) znext = g_z[(size_t)(t + 1) * BH + b * 128 + j];

        ull a0 = 0, a1 = 0, a2 = 0, a3 = 0;
        const ulonglong2* h2 = (const ulonglong2*)hs;
        #pragma unroll
        for (int i = 0; i < 16; i++) {
            ulonglong2 hv = h2[i];
            fma2(a0, hv.x, w[2 * i]);
            fma2(a1, hv.y, w[2 * i + 1]);
        }
        #pragma unroll
        for (int i = 16; i < 32; i++) {
            ulonglong2 hv = h2[i];
            fma2(a2, hv.x, w[2 * i]);
            fma2(a3, hv.y, w[2 * i + 1]);
        }
        float2 f0 = upk2(a0), f1 = upk2(a1), f2 = upk2(a2), f3 = upk2(a3);
        float s = ((f0.x + f0.y) + (f1.x + f1.y)) + ((f2.x + f2.y) + (f3.x + f3.y));
        float hn = tanhf(s + zreg + bh);

        __syncthreads();                 // all reads of hs done
        hs[j] = hn;
        g_h[(size_t)(t + 1) * BH + b * 128 + j] = hn;
        zreg = znext;
        __syncthreads();                 // new hs visible
    }
}

// =====================================================================
extern "C" void kernel_launch(void* const* d_in, const int* in_sizes, int n_in,
                              void* d_out, int out_size)
{
    const float* x    = (const float*)d_in[0];
    const float* W_x  = (const float*)d_in[1];
    const float* b_x  = (const float*)d_in[2];
    const float* W_ih = (const float*)d_in[3];
    const float* b_ih = (const float*)d_in[4];
    const float* W_hh = (const float*)d_in[5];
    const float* b_hh = (const float*)d_in[6];
    const float* W_h  = (const float*)d_in[7];
    const float* b_h  = (const float*)d_in[8];
    const float* W_g  = (const float*)d_in[9];
    const float* b_g  = (const float*)d_in[10];
    float* y = (float*)d_out;

    cudaFuncSetAttribute(phase1_mma, cudaFuncAttributeMaxDynamicSharedMemorySize, P1_DYN);
    cudaFuncSetAttribute(phase3_mma, cudaFuncAttributeMaxDynamicSharedMemorySize, P3_DYN);

    split_weights_kernel<<<192, 256>>>(W_x, W_ih, W_h, W_g);
    phase1_mma<<<PGRID, PTHREADS, P1_DYN>>>(x, b_x, b_ih);
    rnn_kernel<<<B_DIM, 128>>>(W_hh, b_hh);
    phase3_mma<<<PGRID, PTHREADS, P3_DYN>>>(b_h, b_g, y);
}

// round 16
// speedup vs baseline: 1.0363x; 1.0363x over previous
#include <cuda_runtime.h>
#include <cuda_bf16.h>
#include <math.h>
#include <stdint.h>

typedef unsigned long long ull;

#define T_LEN 1024
#define B_DIM 256
#define H_DIM 128
#define BH (B_DIM * H_DIM)          // 32768
#define R_TOT (T_LEN * B_DIM)       // 262144
#define N_TILES (R_TOT / 128)       // 2048
#define PGRID 148                   // persistent grid: one CTA per SM

__device__ float g_z[(size_t)T_LEN * BH];
__device__ float g_h[(size_t)T_LEN * BH];

// Pre-split weight images, padded to the exact smem layouts (bf16)
__device__ __align__(16) __nv_bfloat16 g_wx_h[128 * 72],  g_wx_l[128 * 72];    // LDA1=72
__device__ __align__(16) __nv_bfloat16 g_wih_h[128 * 136], g_wih_l[128 * 136]; // LDW=136
__device__ __align__(16) __nv_bfloat16 g_wh_h[128 * 136],  g_wh_l[128 * 136];
__device__ __align__(16) __nv_bfloat16 g_wg_h[64 * 136],   g_wg_l[64 * 136];

// ---------------- helpers ----------------
__device__ __forceinline__ uint32_t smaddr(const void* p) {
    uint32_t a;
    asm("{ .reg .u64 t; cvta.to.shared.u64 t, %1; cvt.u32.u64 %0, t; }" : "=r"(a) : "l"(p));
    return a;
}
__device__ __forceinline__ uint32_t cvt_bf2(float lo, float hi) {
    uint32_t r;
    asm("cvt.rn.bf16x2.f32 %0, %1, %2;" : "=r"(r) : "f"(hi), "f"(lo));
    return r;
}
__device__ __forceinline__ float lo2f(uint32_t w) { return __uint_as_float(w << 16); }
__device__ __forceinline__ float hi2f(uint32_t w) { return __uint_as_float(w & 0xFFFF0000u); }
__device__ __forceinline__ void split2(float vx, float vy, uint32_t& hi, uint32_t& lo) {
    hi = cvt_bf2(vx, vy);
    lo = cvt_bf2(vx - lo2f(hi), vy - hi2f(hi));
}

#define LDSM4(r0, r1, r2, r3, addr) \
    asm volatile("ldmatrix.sync.aligned.m8n8.x4.shared.b16 {%0,%1,%2,%3}, [%4];" \
                 : "=r"(r0), "=r"(r1), "=r"(r2), "=r"(r3) : "r"(addr))

__device__ __forceinline__ void mma16816(float* d, uint32_t a0, uint32_t a1, uint32_t a2, uint32_t a3,
                                         uint32_t b0, uint32_t b1) {
    asm volatile(
        "mma.sync.aligned.m16n8k16.row.col.f32.bf16.bf16.f32 "
        "{%0,%1,%2,%3}, {%4,%5,%6,%7}, {%8,%9}, {%0,%1,%2,%3};"
        : "+f"(d[0]), "+f"(d[1]), "+f"(d[2]), "+f"(d[3])
        : "r"(a0), "r"(a1), "r"(a2), "r"(a3), "r"(b0), "r"(b1));
}

// Warp-level split-bf16 GEMM: acc[MT][NT][4] += (Ahi+Alo) @ (Bhi+Blo)^T (3 combos)
template<int MT, int NT, int KS, int LDA, int LDB>
__device__ __forceinline__ void warp_gemm3(
    uint32_t Ah, uint32_t Al, uint32_t Bh, uint32_t Bl,
    int mbase, int nbase, int lane, float (&acc)[MT][NT][4])
{
    const uint32_t dA = Al - Ah;
    const uint32_t dB = Bl - Bh;
    uint32_t aAddr[MT];
    #pragma unroll
    for (int mt = 0; mt < MT; mt++)
        aAddr[mt] = Ah + (uint32_t)(((mbase + mt * 16 + (lane & 15)) * LDA + (lane >> 4) * 8) * 2);
    uint32_t bAddr[NT / 2];
    #pragma unroll
    for (int p = 0; p < NT / 2; p++)
        bAddr[p] = Bh + (uint32_t)(((nbase + p * 16 + (lane >> 4) * 8 + (lane & 7)) * LDB
                                    + ((lane >> 3) & 1) * 8) * 2);

    #pragma unroll
    for (int ks = 0; ks < KS; ks++) {
        const uint32_t ko = ks * 32;
        uint32_t ah[MT][4], al[MT][4];
        #pragma unroll
        for (int mt = 0; mt < MT; mt++) {
            LDSM4(ah[mt][0], ah[mt][1], ah[mt][2], ah[mt][3], aAddr[mt] + ko);
            LDSM4(al[mt][0], al[mt][1], al[mt][2], al[mt][3], aAddr[mt] + ko + dA);
        }
        uint32_t bh[NT][2], bl[NT][2];
        #pragma unroll
        for (int p = 0; p < NT / 2; p++) {
            LDSM4(bh[2 * p][0], bh[2 * p][1], bh[2 * p + 1][0], bh[2 * p + 1][1], bAddr[p] + ko);
            LDSM4(bl[2 * p][0], bl[2 * p][1], bl[2 * p + 1][0], bl[2 * p + 1][1], bAddr[p] + ko + dB);
        }
        #pragma unroll
        for (int mt = 0; mt < MT; mt++)
            #pragma unroll
            for (int nt = 0; nt < NT; nt++) {
                mma16816(acc[mt][nt], ah[mt][0], ah[mt][1], ah[mt][2], ah[mt][3], bh[nt][0], bh[nt][1]);
                mma16816(acc[mt][nt], ah[mt][0], ah[mt][1], ah[mt][2], ah[mt][3], bl[nt][0], bl[nt][1]);
                mma16816(acc[mt][nt], al[mt][0], al[mt][1], al[mt][2], al[mt][3], bh[nt][0], bh[nt][1]);
            }
    }
}

__device__ __forceinline__ void cp16(void* d, const void* s, int bytes, int tid, int nthr) {
    uint4* dd = (uint4*)d;
    const uint4* ss = (const uint4*)s;
    for (int i = tid; i < bytes / 16; i += nthr) dd[i] = ss[i];
}

// =====================================================================
// Weight pre-split (once per launch)
// =====================================================================
__global__ void split_weights_kernel(const float* __restrict__ Wx, const float* __restrict__ Wih,
                                     const float* __restrict__ Wh, const float* __restrict__ Wg)
{
    int idx = blockIdx.x * 256 + threadIdx.x;
    const float* W; __nv_bfloat16 *hi, *lo; int K, LD, local;
    if (idx < 8192)       { W = Wx;  hi = g_wx_h;  lo = g_wx_l;  K = 64;  LD = 72;  local = idx; }
    else if (idx < 24576) { W = Wih; hi = g_wih_h; lo = g_wih_l; K = 128; LD = 136; local = idx - 8192; }
    else if (idx < 40960) { W = Wh;  hi = g_wh_h;  lo = g_wh_l;  K = 128; LD = 136; local = idx - 24576; }
    else if (idx < 49152) { W = Wg;  hi = g_wg_h;  lo = g_wg_l;  K = 128; LD = 136; local = idx - 40960; }
    else return;
    int n = local / K, k = local % K;
    float v = W[local];
    __nv_bfloat16 h = __float2bfloat16(v);
    float r = v - __bfloat162float(h);
    hi[n * LD + k] = h;
    lo[n * LD + k] = __float2bfloat16(r);
}

// =====================================================================
// Phase 1: z = tanh(x @ Wx^T + b_x) @ Wih^T + b_ih        [R_TOT, 128]
// Persistent, 512 threads (16 warps = 4/SMSP), warp grid 8m x 2n.
// (measured-best config for phase1: 158 us)
// =====================================================================
#define P1T 512
#define LDA1 72
#define LDW  136
#define P1_A1H 0
#define P1_A1L 18432
#define P1_B1H 36864
#define P1_B1L 55296
#define P1_B2H 73728
#define P1_B2L 108544
#define P1_FH  143360
#define P1_FL  178176
#define P1_DYN 212992

__global__ __launch_bounds__(P1T) void phase1_mma(
    const float* __restrict__ x, const float* __restrict__ b_x,
    const float* __restrict__ b_ih)
{
    extern __shared__ __align__(16) unsigned char sm[];
    __shared__ float s_bx[128], s_bih[128];

    const int tid = threadIdx.x, lane = tid & 31, wid = tid >> 5;
    const int wm = wid >> 1, wn = wid & 1;          // 8m x 2n
    const uint32_t sb = smaddr(sm);

    if (tid < 128) { s_bx[tid] = b_x[tid]; s_bih[tid] = b_ih[tid]; }

    // weights: loaded ONCE per CTA
    cp16(sm + P1_B1H, g_wx_h, 18432, tid, P1T);
    cp16(sm + P1_B1L, g_wx_l, 18432, tid, P1T);
    cp16(sm + P1_B2H, g_wih_h, 34816, tid, P1T);
    cp16(sm + P1_B2L, g_wih_l, 34816, tid, P1T);

    for (int tile = blockIdx.x; tile < N_TILES; tile += PGRID) {
        const int row0 = tile * 128;

        // x tile [128m][64k] -> split (no live readers of A1 here)
        {
            const float2* xg = (const float2*)(x + (size_t)row0 * 64);
            for (int p = tid; p < 4096; p += P1T) {
                int m = p >> 5, kp = (p & 31) * 2;
                float2 v = xg[p];
                uint32_t hi, lo; split2(v.x, v.y, hi, lo);
                *(uint32_t*)(sm + P1_A1H + (m * LDA1 + kp) * 2) = hi;
                *(uint32_t*)(sm + P1_A1L + (m * LDA1 + kp) * 2) = lo;
            }
        }
        __syncthreads();

        float acc[1][8][4];
        #pragma unroll
        for (int b = 0; b < 8; b++)
            #pragma unroll
            for (int c = 0; c < 4; c++) acc[0][b][c] = 0.0f;

        warp_gemm3<1, 8, 4, LDA1, LDA1>(sb + P1_A1H, sb + P1_A1L, sb + P1_B1H, sb + P1_B1L,
                                        wm * 16, wn * 64, lane, acc);

        #pragma unroll
        for (int nt = 0; nt < 8; nt++) {
            int row = wm * 16 + (lane >> 2);
            int col = wn * 64 + nt * 8 + 2 * (lane & 3);
            float t0 = tanhf(acc[0][nt][0] + s_bx[col]);
            float t1 = tanhf(acc[0][nt][1] + s_bx[col + 1]);
            uint32_t hi, lo; split2(t0, t1, hi, lo);
            *(uint32_t*)(sm + P1_FH + (row * LDW + col) * 2) = hi;
            *(uint32_t*)(sm + P1_FL + (row * LDW + col) * 2) = lo;
            float t2 = tanhf(acc[0][nt][2] + s_bx[col]);
            float t3 = tanhf(acc[0][nt][3] + s_bx[col + 1]);
            split2(t2, t3, hi, lo);
            *(uint32_t*)(sm + P1_FH + ((row + 8) * LDW + col) * 2) = hi;
            *(uint32_t*)(sm + P1_FL + ((row + 8) * LDW + col) * 2) = lo;
        }
        __syncthreads();

        #pragma unroll
        for (int b = 0; b < 8; b++)
            #pragma unroll
            for (int c = 0; c < 4; c++) acc[0][b][c] = 0.0f;

        warp_gemm3<1, 8, 8, LDW, LDW>(sb + P1_FH, sb + P1_FL, sb + P1_B2H, sb + P1_B2L,
                                      wm * 16, wn * 64, lane, acc);

        #pragma unroll
        for (int nt = 0; nt < 8; nt++) {
            int row = row0 + wm * 16 + (lane >> 2);
            int col = wn * 64 + nt * 8 + 2 * (lane & 3);
            float2 v0 = make_float2(acc[0][nt][0] + s_bih[col], acc[0][nt][1] + s_bih[col + 1]);
            float2 v1 = make_float2(acc[0][nt][2] + s_bih[col], acc[0][nt][3] + s_bih[col + 1]);
            *(float2*)(g_z + (size_t)row * 128 + col) = v0;
            *(float2*)(g_z + (size_t)(row + 8) * 128 + col) = v1;
        }
    }
}

// =====================================================================
// Phase 3: y = tanh(h @ Wh^T + b_h) @ Wg^T + b_g          [R_TOT, 64]
// Persistent, 1024 threads (32 warps = 8/SMSP), warp grid 8m x 4n.
// (measured-best config for phase3: 145 us)
// =====================================================================
#define P3T 1024
#define P3_A1H 0
#define P3_A1L 34816
#define P3_B1H 69632
#define P3_B1L 104448
#define P3_B2H 139264
#define P3_B2L 156672
#define P3_DYN 174080

__global__ __launch_bounds__(P3T) void phase3_mma(
    const float* __restrict__ b_h, const float* __restrict__ b_g,
    float* __restrict__ y)
{
    extern __shared__ __align__(16) unsigned char sm[];
    __shared__ float s_bh[128], s_bg[64];

    const int tid = threadIdx.x, lane = tid & 31, wid = tid >> 5;
    const int wm = wid >> 2, wn = wid & 3;          // 8m x 4n
    const uint32_t sb = smaddr(sm);

    if (tid < 128) s_bh[tid] = b_h[tid];
    if (tid < 64)  s_bg[tid] = b_g[tid];

    cp16(sm + P3_B1H, g_wh_h, 34816, tid, P3T);
    cp16(sm + P3_B1L, g_wh_l, 34816, tid, P3T);
    cp16(sm + P3_B2H, g_wg_h, 17408, tid, P3T);
    cp16(sm + P3_B2L, g_wg_l, 17408, tid, P3T);

    bool first = true;
    for (int tile = blockIdx.x; tile < N_TILES; tile += PGRID) {
        const int row0 = tile * 128;

        if (!first) __syncthreads();   // gemm2 readers of A1 (u) must finish
        first = false;

        // h tile [128m][128k] -> split
        {
            const float2* hg = (const float2*)(g_h + (size_t)row0 * 128);
            for (int p = tid; p < 8192; p += P3T) {
                int m = p >> 6, kp = (p & 63) * 2;
                float2 v = hg[p];
                uint32_t hi, lo; split2(v.x, v.y, hi, lo);
                *(uint32_t*)(sm + P3_A1H + (m * LDW + kp) * 2) = hi;
                *(uint32_t*)(sm + P3_A1L + (m * LDW + kp) * 2) = lo;
            }
        }
        __syncthreads();

        float acc[1][4][4];
        #pragma unroll
        for (int b = 0; b < 4; b++)
            #pragma unroll
            for (int c = 0; c < 4; c++) acc[0][b][c] = 0.0f;

        warp_gemm3<1, 4, 8, LDW, LDW>(sb + P3_A1H, sb + P3_A1L, sb + P3_B1H, sb + P3_B1L,
                                      wm * 16, wn * 32, lane, acc);
        __syncthreads();   // all reads of A1 done before in-place overwrite

        #pragma unroll
        for (int nt = 0; nt < 4; nt++) {
            int row = wm * 16 + (lane >> 2);
            int col = wn * 32 + nt * 8 + 2 * (lane & 3);
            float t0 = tanhf(acc[0][nt][0] + s_bh[col]);
            float t1 = tanhf(acc[0][nt][1] + s_bh[col + 1]);
            uint32_t hi, lo; split2(t0, t1, hi, lo);
            *(uint32_t*)(sm + P3_A1H + (row * LDW + col) * 2) = hi;
            *(uint32_t*)(sm + P3_A1L + (row * LDW + col) * 2) = lo;
            float t2 = tanhf(acc[0][nt][2] + s_bh[col]);
            float t3 = tanhf(acc[0][nt][3] + s_bh[col + 1]);
            split2(t2, t3, hi, lo);
            *(uint32_t*)(sm + P3_A1H + ((row + 8) * LDW + col) * 2) = hi;
            *(uint32_t*)(sm + P3_A1L + ((row + 8) * LDW + col) * 2) = lo;
        }
        __syncthreads();

        float ac2[1][2][4];
        #pragma unroll
        for (int b = 0; b < 2; b++)
            #pragma unroll
            for (int c = 0; c < 4; c++) ac2[0][b][c] = 0.0f;

        warp_gemm3<1, 2, 8, LDW, LDW>(sb + P3_A1H, sb + P3_A1L, sb + P3_B2H, sb + P3_B2L,
                                      wm * 16, wn * 16, lane, ac2);

        #pragma unroll
        for (int nt = 0; nt < 2; nt++) {
            int row = row0 + wm * 16 + (lane >> 2);
            int col = wn * 16 + nt * 8 + 2 * (lane & 3);
            float2 v0 = make_float2(ac2[0][nt][0] + s_bg[col], ac2[0][nt][1] + s_bg[col + 1]);
            float2 v1 = make_float2(ac2[0][nt][2] + s_bg[col], ac2[0][nt][3] + s_bg[col + 1]);
            *(float2*)(y + (size_t)row * 64 + col) = v0;
            *(float2*)(y + (size_t)(row + 8) * 64 + col) = v1;
        }
    }
}

// =====================================================================
// Phase 2: recurrence — EXACT round-1 measured-best version (untouched).
// =====================================================================
__device__ __forceinline__ ull pk2(float lo, float hi) {
    ull r;
    asm("mov.b64 %0, {%1,%2};" : "=l"(r) : "r"(__float_as_uint(lo)), "r"(__float_as_uint(hi)));
    return r;
}
__device__ __forceinline__ float2 upk2(ull v) {
    unsigned int lo, hi;
    asm("mov.b64 {%0,%1}, %2;" : "=r"(lo), "=r"(hi) : "l"(v));
    return make_float2(__uint_as_float(lo), __uint_as_float(hi));
}
__device__ __forceinline__ void fma2(ull& d, ull a, ull b) {
    asm("fma.rn.f32x2 %0, %1, %2, %0;" : "+l"(d) : "l"(a), "l"(b));
}

__global__ __launch_bounds__(128, 3) void rnn_kernel(
    const float* __restrict__ W_hh, const float* __restrict__ b_hh)
{
    __shared__ __align__(16) float hs[128];

    const int b = blockIdx.x;
    const int j = threadIdx.x;

    ull w[64];
    const ulonglong2* w2 = (const ulonglong2*)(W_hh + j * 128);
    #pragma unroll
    for (int i = 0; i < 32; i++) {
        ulonglong2 v = w2[i];
        w[2 * i]     = v.x;
        w[2 * i + 1] = v.y;
    }
    const float bh = b_hh[j];

    hs[j] = 0.0f;
    g_h[(size_t)b * 128 + j] = 0.0f;                 // h_0 = 0
    float zreg = g_z[(size_t)b * 128 + j];           // z_0
    __syncthreads();

    for (int t = 0; t < T_LEN - 1; ++t) {
        float znext = 0.0f;
        if (t < T_LEN - 2) znext = g_z[(size_t)(t + 1) * BH + b * 128 + j];

        ull a0 = 0, a1 = 0, a2 = 0, a3 = 0;
        const ulonglong2* h2 = (const ulonglong2*)hs;
        #pragma unroll
        for (int i = 0; i < 16; i++) {
            ulonglong2 hv = h2[i];
            fma2(a0, hv.x, w[2 * i]);
            fma2(a1, hv.y, w[2 * i + 1]);
        }
        #pragma unroll
        for (int i = 16; i < 32; i++) {
            ulonglong2 hv = h2[i];
            fma2(a2, hv.x, w[2 * i]);
            fma2(a3, hv.y, w[2 * i + 1]);
        }
        float2 f0 = upk2(a0), f1 = upk2(a1), f2 = upk2(a2), f3 = upk2(a3);
        float s = ((f0.x + f0.y) + (f1.x + f1.y)) + ((f2.x + f2.y) + (f3.x + f3.y));
        float hn = tanhf(s + zreg + bh);

        __syncthreads();                 // all reads of hs done
        hs[j] = hn;
        g_h[(size_t)(t + 1) * BH + b * 128 + j] = hn;
        zreg = znext;
        __syncthreads();                 // new hs visible
    }
}

// =====================================================================
extern "C" void kernel_launch(void* const* d_in, const int* in_sizes, int n_in,
                              void* d_out, int out_size)
{
    const float* x    = (const float*)d_in[0];
    const float* W_x  = (const float*)d_in[1];
    const float* b_x  = (const float*)d_in[2];
    const float* W_ih = (const float*)d_in[3];
    const float* b_ih = (const float*)d_in[4];
    const float* W_hh = (const float*)d_in[5];
    const float* b_hh = (const float*)d_in[6];
    const float* W_h  = (const float*)d_in[7];
    const float* b_h  = (const float*)d_in[8];
    const float* W_g  = (const float*)d_in[9];
    const float* b_g  = (const float*)d_in[10];
    float* y = (float*)d_out;

    cudaFuncSetAttribute(phase1_mma, cudaFuncAttributeMaxDynamicSharedMemorySize, P1_DYN);
    cudaFuncSetAttribute(phase3_mma, cudaFuncAttributeMaxDynamicSharedMemorySize, P3_DYN);

    split_weights_kernel<<<192, 256>>>(W_x, W_ih, W_h, W_g);
    phase1_mma<<<PGRID, P1T, P1_DYN>>>(x, b_x, b_ih);
    rnn_kernel<<<B_DIM, 128>>>(W_hh, b_hh);
    phase3_mma<<<PGRID, P3T, P3_DYN>>>(b_h, b_g, y);
}